// round 1
// baseline (speedup 1.0000x reference)
#include <cuda_runtime.h>
#include <math.h>

#define DM 1024
#define NH 16
#define HD 64
#define B_ 2
#define T_ 2048
#define ROWS (B_*T_)

// Scratch (static device globals — allocation-free per harness rules)
__device__ float g_q[(size_t)B_*NH*T_*HD];     // [B,H,T,hd]
__device__ float g_k[(size_t)B_*NH*T_*HD];
__device__ float g_v[(size_t)B_*NH*T_*HD];
__device__ float g_attn[(size_t)ROWS*DM];      // [B,T,D]

// ---------------------------------------------------------------------------
// Tiled fp32 GEMM: C[M,N] = A[M,K] @ B[K,N], 64x64 tile, BK=16, 4x4 per thread.
// splitHeads=1 scatters output into [B,H,T,hd] layout (for Q/K/V).
// ---------------------------------------------------------------------------
__global__ __launch_bounds__(256)
void gemm_kernel(const float* __restrict__ A, const float* __restrict__ B,
                 float* __restrict__ C, int K, int N, int splitHeads)
{
    __shared__ float As[16][64];   // transposed: As[k][m]
    __shared__ float Bs[16][64];
    const int tid = threadIdx.x;
    const int tx = tid & 15, ty = tid >> 4;
    const int bm = blockIdx.y << 6, bn = blockIdx.x << 6;
    float acc[4][4] = {};

    const int arow = tid >> 2, acol = (tid & 3) << 2;
    const int brow = tid >> 4, bcol = (tid & 15) << 2;
    const float* Ap = A + (size_t)(bm + arow) * K + acol;
    const float* Bp = B + (size_t)brow * N + bn + bcol;

    for (int k0 = 0; k0 < K; k0 += 16) {
        float4 a4 = *(const float4*)(Ap + k0);
        float4 b4 = *(const float4*)(Bp + (size_t)k0 * N);
        As[acol + 0][arow] = a4.x;
        As[acol + 1][arow] = a4.y;
        As[acol + 2][arow] = a4.z;
        As[acol + 3][arow] = a4.w;
        *(float4*)&Bs[brow][bcol] = b4;
        __syncthreads();
#pragma unroll
        for (int kk = 0; kk < 16; kk++) {
            float4 av = *(const float4*)&As[kk][ty << 2];
            float4 bv = *(const float4*)&Bs[kk][tx << 2];
            float ar[4] = {av.x, av.y, av.z, av.w};
            float br[4] = {bv.x, bv.y, bv.z, bv.w};
#pragma unroll
            for (int i = 0; i < 4; i++)
#pragma unroll
                for (int j = 0; j < 4; j++)
                    acc[i][j] = fmaf(ar[i], br[j], acc[i][j]);
        }
        __syncthreads();
    }

#pragma unroll
    for (int i = 0; i < 4; i++) {
        int m = bm + (ty << 2) + i;
        int n = bn + (tx << 2);
        float4 r = make_float4(acc[i][0], acc[i][1], acc[i][2], acc[i][3]);
        if (!splitHeads) {
            *(float4*)&C[(size_t)m * N + n] = r;
        } else {
            int b = m >> 11, t = m & (T_ - 1);
            int h = n >> 6, d = n & (HD - 1);
            *(float4*)&C[((size_t)((b * NH + h) << 11) + t) * HD + d] = r;
        }
    }
}

// ---------------------------------------------------------------------------
// Fused per-head RMSNorm + RoPE, in place on [B,H,T,hd]. One warp per row.
// lane handles elements (lane, lane+32) == RoPE pair (x1, x2).
// ---------------------------------------------------------------------------
__global__ __launch_bounds__(256)
void rmsrope_kernel(float* __restrict__ X, const float* __restrict__ w)
{
    int row = blockIdx.x * 8 + (threadIdx.x >> 5);
    int lane = threadIdx.x & 31;
    float* p = X + (size_t)row * HD;
    float x1 = p[lane], x2 = p[lane + 32];
    float ss = x1 * x1 + x2 * x2;
#pragma unroll
    for (int off = 16; off; off >>= 1)
        ss += __shfl_xor_sync(0xffffffffu, ss, off);
    float rms = rsqrtf(ss * (1.0f / HD) + 1e-6f);
    float n1 = x1 * rms * w[lane];
    float n2 = x2 * rms * w[lane + 32];
    int t = row & (T_ - 1);
    float freq = (float)t * powf(10000.0f, -(float)(2 * lane) * (1.0f / HD));
    float sn, cs;
    sincosf(freq, &sn, &cs);
    p[lane]      = n1 * cs - n2 * sn;
    p[lane + 32] = n2 * cs + n1 * sn;
}

// ---------------------------------------------------------------------------
// Flash attention (fp32, causal), 64 queries x 64 keys per tile.
// Online softmax in registers; P staged via smem (unioned with K^T buffer).
// Output written directly to [B,T,D] layout for the O-projection GEMM.
// ---------------------------------------------------------------------------
extern __shared__ float fsm[];
__global__ __launch_bounds__(256)
void flash_kernel(const float* __restrict__ Q, const float* __restrict__ K,
                  const float* __restrict__ V, float* __restrict__ O)
{
    float* Qs = fsm;                     // [64][64]       4096 floats
    float* Vs = fsm + 4096;             // [64][68]       4352 floats
    float* KP = fsm + 4096 + 4352;      // [64][65] union 4160 floats (K^T, then P)

    const int tid = threadIdx.x;
    const int tx = tid & 15, ty = tid >> 4;
    const int bh = blockIdx.y;
    const int qt = blockIdx.x;
    const int q0 = qt << 6;
    const float* Qg = Q + ((size_t)bh * T_ + q0) * HD;
    const float* Kg = K + (size_t)bh * T_ * HD;
    const float* Vg = V + (size_t)bh * T_ * HD;

    // Load Q tile (row stride 64)
    for (int i = tid * 4; i < 64 * 64; i += 1024)
        *(float4*)&Qs[i] = *(const float4*)&Qg[i];

    float m[4], l[4], o[4][4];
#pragma unroll
    for (int i = 0; i < 4; i++) {
        m[i] = -1e30f; l[i] = 0.f;
#pragma unroll
        for (int j = 0; j < 4; j++) o[i][j] = 0.f;
    }

    for (int kt = 0; kt <= qt; kt++) {
        const int k0 = kt << 6;
        const bool diag = (kt == qt);
        __syncthreads();   // prior PV reads done before overwriting KP/Vs
        // Load K tile transposed (KP[d][c], stride 65) and V tile (Vs[c][d], stride 68)
        for (int it = tid; it < 64 * 16; it += 256) {
            int c = it >> 4, d4 = (it & 15) << 2;
            float4 kv = *(const float4*)&Kg[(size_t)(k0 + c) * HD + d4];
            KP[(d4 + 0) * 65 + c] = kv.x;
            KP[(d4 + 1) * 65 + c] = kv.y;
            KP[(d4 + 2) * 65 + c] = kv.z;
            KP[(d4 + 3) * 65 + c] = kv.w;
            *(float4*)&Vs[c * 68 + d4] = *(const float4*)&Vg[(size_t)(k0 + c) * HD + d4];
        }
        __syncthreads();

        // S = Q @ K^T (4x4 micro-tile per thread)
        float s[4][4] = {};
#pragma unroll 8
        for (int kk = 0; kk < 64; kk++) {
            float a[4], b[4];
#pragma unroll
            for (int i = 0; i < 4; i++) a[i] = Qs[((ty << 2) + i) * 64 + kk];
#pragma unroll
            for (int j = 0; j < 4; j++) b[j] = KP[kk * 65 + (tx << 2) + j];
#pragma unroll
            for (int i = 0; i < 4; i++)
#pragma unroll
                for (int j = 0; j < 4; j++)
                    s[i][j] = fmaf(a[i], b[j], s[i][j]);
        }

        // Online softmax (row reduce across 16 tx lanes via shfl within half-warp)
        float alpha[4];
#pragma unroll
        for (int i = 0; i < 4; i++) {
            int qi = q0 + (ty << 2) + i;
            float mx = -1e30f;
#pragma unroll
            for (int j = 0; j < 4; j++) {
                int ki = k0 + (tx << 2) + j;
                s[i][j] = (!diag || ki <= qi) ? s[i][j] * 0.125f : -1e30f;
                mx = fmaxf(mx, s[i][j]);
            }
#pragma unroll
            for (int off = 8; off; off >>= 1)
                mx = fmaxf(mx, __shfl_xor_sync(0xffffffffu, mx, off));
            float mn = fmaxf(m[i], mx);
            alpha[i] = expf(m[i] - mn);
            m[i] = mn;
            float rs = 0.f;
#pragma unroll
            for (int j = 0; j < 4; j++) {
                s[i][j] = expf(s[i][j] - mn);
                rs += s[i][j];
            }
#pragma unroll
            for (int off = 8; off; off >>= 1)
                rs += __shfl_xor_sync(0xffffffffu, rs, off);
            l[i] = l[i] * alpha[i] + rs;
#pragma unroll
            for (int j = 0; j < 4; j++) o[i][j] *= alpha[i];
        }

        __syncthreads();   // all threads done reading K^T from KP
        // Stage P into KP (reused buffer)
#pragma unroll
        for (int i = 0; i < 4; i++)
#pragma unroll
            for (int j = 0; j < 4; j++)
                KP[((ty << 2) + i) * 65 + (tx << 2) + j] = s[i][j];
        __syncthreads();

        // O += P @ V
#pragma unroll 8
        for (int c = 0; c < 64; c++) {
            float4 vv = *(const float4*)&Vs[c * 68 + (tx << 2)];
            float vr[4] = {vv.x, vv.y, vv.z, vv.w};
#pragma unroll
            for (int i = 0; i < 4; i++) {
                float p = KP[((ty << 2) + i) * 65 + c];
#pragma unroll
                for (int j = 0; j < 4; j++)
                    o[i][j] = fmaf(p, vr[j], o[i][j]);
            }
        }
    }

    // Epilogue: normalize and write to [B,T,D]
    const int b = bh >> 4, h = bh & (NH - 1);
#pragma unroll
    for (int i = 0; i < 4; i++) {
        int qrow = q0 + (ty << 2) + i;
        float inv = 1.0f / l[i];
        float4 r = make_float4(o[i][0] * inv, o[i][1] * inv, o[i][2] * inv, o[i][3] * inv);
        *(float4*)&O[(size_t)(b * T_ + qrow) * DM + h * HD + (tx << 2)] = r;
    }
}

// ---------------------------------------------------------------------------
extern "C" void kernel_launch(void* const* d_in, const int* in_sizes, int n_in,
                              void* d_out, int out_size)
{
    (void)in_sizes; (void)n_in; (void)out_size;
    const float* x  = (const float*)d_in[0];
    const float* Wq = (const float*)d_in[1];
    const float* Wk = (const float*)d_in[2];
    const float* Wv = (const float*)d_in[3];
    const float* Wo = (const float*)d_in[4];
    const float* qw = (const float*)d_in[5];
    const float* kw = (const float*)d_in[6];
    float* out = (float*)d_out;

    float *qp, *kp, *vp, *ap;
    cudaGetSymbolAddress((void**)&qp, g_q);
    cudaGetSymbolAddress((void**)&kp, g_k);
    cudaGetSymbolAddress((void**)&vp, g_v);
    cudaGetSymbolAddress((void**)&ap, g_attn);

    const int FLASH_SMEM = (4096 + 4352 + 4160) * 4;   // 50432 B
    cudaFuncSetAttribute(flash_kernel,
                         cudaFuncAttributeMaxDynamicSharedMemorySize, FLASH_SMEM);

    dim3 gg(DM / 64, ROWS / 64);   // (16, 64)
    gemm_kernel<<<gg, 256>>>(x, Wq, qp, DM, DM, 1);
    gemm_kernel<<<gg, 256>>>(x, Wk, kp, DM, DM, 1);
    gemm_kernel<<<gg, 256>>>(x, Wv, vp, DM, DM, 1);

    rmsrope_kernel<<<B_ * NH * T_ / 8, 256>>>(qp, qw);
    rmsrope_kernel<<<B_ * NH * T_ / 8, 256>>>(kp, kw);

    flash_kernel<<<dim3(T_ / 64, B_ * NH), 256, FLASH_SMEM>>>(qp, kp, vp, ap);

    gemm_kernel<<<gg, 256>>>(ap, Wo, out, DM, DM, 0);
}

// round 2
// speedup vs baseline: 1.4625x; 1.4625x over previous
#include <cuda_runtime.h>
#include <mma.h>
#include <math.h>

using namespace nvcuda;

#define DM 1024
#define NH 16
#define HD 64
#define B_ 2
#define T_ 2048
#define ROWS (B_*T_)

#define BR 128
#define BC 64
#define LDF 68          // flash smem row pitch (floats)

// Scratch (static device globals — allocation-free per harness rules)
__device__ float g_q[(size_t)B_*NH*T_*HD];     // [B,H,T,hd]
__device__ float g_k[(size_t)B_*NH*T_*HD];
__device__ float g_v[(size_t)B_*NH*T_*HD];
__device__ float g_attn[(size_t)ROWS*DM];      // [B,T,D]

__device__ __forceinline__ float ftf(float x) { return wmma::__float_to_tf32(x); }

// ---------------------------------------------------------------------------
// tf32 wmma GEMM body: C[M,N]=A[M,K]@B[K,N]. 128x128 tile, BK=32, 8 warps.
// Each warp: 64x32 (4x2 fragments of 16x16). K=N=1024 fixed.
// ---------------------------------------------------------------------------
__device__ __forceinline__
void gemm_body(const float* __restrict__ A, const float* __restrict__ Bw,
               float* __restrict__ C, bool splitHeads)
{
    __shared__ float As[128][36];
    __shared__ float Bs[32][132];
    const int K = 1024, N = 1024;
    const int tid = threadIdx.x;
    const int wid = tid >> 5;
    const int warp_m = wid >> 2, warp_n = wid & 3;
    const int bm = blockIdx.y << 7, bn = blockIdx.x << 7;

    wmma::fragment<wmma::accumulator, 16, 16, 8, float> acc[4][2];
#pragma unroll
    for (int i = 0; i < 4; i++)
#pragma unroll
        for (int j = 0; j < 2; j++) wmma::fill_fragment(acc[i][j], 0.0f);

    for (int k0 = 0; k0 < K; k0 += 32) {
#pragma unroll
        for (int t = 0; t < 4; t++) {
            int f = tid + (t << 8);
            // A: 128 rows x 32 cols -> 8 float4 per row
            int ar = f >> 3, ac = (f & 7) << 2;
            float4 a4 = *(const float4*)&A[(size_t)(bm + ar) * K + k0 + ac];
            float4 at = make_float4(ftf(a4.x), ftf(a4.y), ftf(a4.z), ftf(a4.w));
            *(float4*)&As[ar][ac] = at;
            // B: 32 rows x 128 cols -> 32 float4 per row
            int br = f >> 5, bc = (f & 31) << 2;
            float4 b4 = *(const float4*)&Bw[(size_t)(k0 + br) * N + bn + bc];
            float4 bt = make_float4(ftf(b4.x), ftf(b4.y), ftf(b4.z), ftf(b4.w));
            *(float4*)&Bs[br][bc] = bt;
        }
        __syncthreads();
#pragma unroll
        for (int ks = 0; ks < 4; ks++) {
            wmma::fragment<wmma::matrix_a, 16, 16, 8, wmma::precision::tf32, wmma::row_major> af[4];
            wmma::fragment<wmma::matrix_b, 16, 16, 8, wmma::precision::tf32, wmma::row_major> bf[2];
#pragma unroll
            for (int i = 0; i < 4; i++)
                wmma::load_matrix_sync(af[i], &As[warp_m * 64 + i * 16][ks * 8], 36);
#pragma unroll
            for (int j = 0; j < 2; j++)
                wmma::load_matrix_sync(bf[j], &Bs[ks * 8][warp_n * 32 + j * 16], 132);
#pragma unroll
            for (int i = 0; i < 4; i++)
#pragma unroll
                for (int j = 0; j < 2; j++)
                    wmma::mma_sync(acc[i][j], af[i], bf[j], acc[i][j]);
        }
        __syncthreads();
    }

#pragma unroll
    for (int i = 0; i < 4; i++)
#pragma unroll
        for (int j = 0; j < 2; j++) {
            int m0 = bm + warp_m * 64 + i * 16;
            int n0 = bn + warp_n * 32 + j * 16;
            if (splitHeads) {
                int b = m0 >> 11, t = m0 & (T_ - 1);
                int h = n0 >> 6, d = n0 & (HD - 1);
                float* p = C + ((size_t)(b * NH + h) * T_ + t) * HD + d;
                wmma::store_matrix_sync(p, acc[i][j], HD, wmma::mem_row_major);
            } else {
                wmma::store_matrix_sync(C + (size_t)m0 * N + n0, acc[i][j], N,
                                        wmma::mem_row_major);
            }
        }
}

__global__ __launch_bounds__(256)
void qkv_gemm(const float* __restrict__ X,
              const float* __restrict__ Wq, const float* __restrict__ Wk,
              const float* __restrict__ Wv,
              float* __restrict__ Q, float* __restrict__ K, float* __restrict__ V)
{
    const float* W; float* C;
    if (blockIdx.z == 0)      { W = Wq; C = Q; }
    else if (blockIdx.z == 1) { W = Wk; C = K; }
    else                      { W = Wv; C = V; }
    gemm_body(X, W, C, true);
}

__global__ __launch_bounds__(256)
void oproj_gemm(const float* __restrict__ A, const float* __restrict__ W,
                float* __restrict__ C)
{
    gemm_body(A, W, C, false);
}

// ---------------------------------------------------------------------------
// Fused per-head RMSNorm + RoPE, in place on [B,H,T,hd]. One warp per row.
// ---------------------------------------------------------------------------
__global__ __launch_bounds__(256)
void rmsrope_kernel(float* __restrict__ X, const float* __restrict__ w)
{
    int row = blockIdx.x * 8 + (threadIdx.x >> 5);
    int lane = threadIdx.x & 31;
    float* p = X + (size_t)row * HD;
    float x1 = p[lane], x2 = p[lane + 32];
    float ss = x1 * x1 + x2 * x2;
#pragma unroll
    for (int off = 16; off; off >>= 1)
        ss += __shfl_xor_sync(0xffffffffu, ss, off);
    float rms = rsqrtf(ss * (1.0f / HD) + 1e-6f);
    float n1 = x1 * rms * w[lane];
    float n2 = x2 * rms * w[lane + 32];
    int t = row & (T_ - 1);
    float freq = (float)t * powf(10000.0f, -(float)(2 * lane) * (1.0f / HD));
    float sn, cs;
    sincosf(freq, &sn, &cs);
    p[lane]      = n1 * cs - n2 * sn;
    p[lane + 32] = n2 * cs + n1 * sn;
}

// ---------------------------------------------------------------------------
// Flash attention, tf32 wmma, causal. Br=128 x Bc=64 tiles, 8 warps.
// Warp w owns rows [16w,16w+16): S frags, softmax, PV frags, O update —
// everything row-strip-local, so only 2 __syncthreads per key tile.
// ---------------------------------------------------------------------------
extern __shared__ float fsm[];
__global__ __launch_bounds__(256)
void flash_kernel(const float* __restrict__ Q, const float* __restrict__ K,
                  const float* __restrict__ V, float* __restrict__ O)
{
    float* Qs = fsm;                          // BR*LDF
    float* Ks = Qs + BR * LDF;                // BC*LDF
    float* Vs = Ks + BC * LDF;                // BC*LDF
    float* Ss = Vs + BC * LDF;                // BR*LDF (S, then P, then PV)
    float* Os = Ss + BR * LDF;                // BR*LDF

    const int tid = threadIdx.x;
    const int wid = tid >> 5;
    const int qt = gridDim.x - 1 - blockIdx.x;   // heavy tiles first
    const int q0 = qt << 7;
    const int bh = blockIdx.y;
    const float* Qg = Q + ((size_t)bh * T_ + q0) * HD;
    const float* Kg = K + (size_t)bh * T_ * HD;
    const float* Vg = V + (size_t)bh * T_ * HD;

    // Load Q tile (tf32) + zero O accumulator
    for (int f = tid; f < BR * HD / 4; f += 256) {
        int r = f >> 4, c = (f & 15) << 2;
        float4 q4 = *(const float4*)&Qg[(size_t)r * HD + c];
        *(float4*)&Qs[r * LDF + c] = make_float4(ftf(q4.x), ftf(q4.y), ftf(q4.z), ftf(q4.w));
        *(float4*)&Os[r * LDF + c] = make_float4(0.f, 0.f, 0.f, 0.f);
    }

    const int rown = tid >> 1;            // row this thread owns (== warp strip)
    const int c0 = (tid & 1) << 5;        // half-row offset
    float m_r = -1e30f, l_r = 0.f;
    const int nkt = 2 * (qt + 1);

    for (int kt = 0; kt < nkt; kt++) {
        const int k0 = kt << 6;
        __syncthreads();
        // Load K,V tiles (tf32)
        for (int f = tid; f < BC * HD / 4; f += 256) {
            int r = f >> 4, c = (f & 15) << 2;
            float4 k4 = *(const float4*)&Kg[(size_t)(k0 + r) * HD + c];
            float4 v4 = *(const float4*)&Vg[(size_t)(k0 + r) * HD + c];
            *(float4*)&Ks[r * LDF + c] = make_float4(ftf(k4.x), ftf(k4.y), ftf(k4.z), ftf(k4.w));
            *(float4*)&Vs[r * LDF + c] = make_float4(ftf(v4.x), ftf(v4.y), ftf(v4.z), ftf(v4.w));
        }
        __syncthreads();

        // S = Q @ K^T  (warp strip 16 x 64)
        {
            wmma::fragment<wmma::accumulator, 16, 16, 8, float> s[4];
#pragma unroll
            for (int c = 0; c < 4; c++) wmma::fill_fragment(s[c], 0.0f);
#pragma unroll
            for (int d0 = 0; d0 < HD; d0 += 8) {
                wmma::fragment<wmma::matrix_a, 16, 16, 8, wmma::precision::tf32, wmma::row_major> af;
                wmma::load_matrix_sync(af, &Qs[(wid * 16) * LDF + d0], LDF);
#pragma unroll
                for (int c = 0; c < 4; c++) {
                    wmma::fragment<wmma::matrix_b, 16, 16, 8, wmma::precision::tf32, wmma::col_major> bf;
                    wmma::load_matrix_sync(bf, &Ks[(c * 16) * LDF + d0], LDF);
                    wmma::mma_sync(s[c], af, bf, s[c]);
                }
            }
#pragma unroll
            for (int c = 0; c < 4; c++)
                wmma::store_matrix_sync(&Ss[(wid * 16) * LDF + c * 16], s[c], LDF,
                                        wmma::mem_row_major);
        }
        __syncwarp();

        // Online softmax on the owned half-row (32 elems)
        float alpha;
        {
            const int lim = q0 + rown - k0;   // valid keys: c <= lim (tile-local)
            float ls[32];
            float mx = -1e30f;
#pragma unroll
            for (int c = 0; c < 32; c++) {
                float s = Ss[rown * LDF + c0 + c] * 0.125f;
                if (c0 + c > lim) s = -1e30f;
                ls[c] = s;
                mx = fmaxf(mx, s);
            }
            mx = fmaxf(mx, __shfl_xor_sync(0xffffffffu, mx, 1));
            float newm = fmaxf(m_r, mx);
            alpha = __expf(m_r - newm);
            m_r = newm;
            float sum = 0.f;
#pragma unroll
            for (int c = 0; c < 32; c++) {
                float p = __expf(ls[c] - newm);
                sum += p;
                Ss[rown * LDF + c0 + c] = ftf(p);
            }
            sum += __shfl_xor_sync(0xffffffffu, sum, 1);
            l_r = l_r * alpha + sum;
        }
        __syncwarp();

        // PV (warp strip 16 x 64), result back into Ss strip
        {
            wmma::fragment<wmma::accumulator, 16, 16, 8, float> pv[4];
#pragma unroll
            for (int c = 0; c < 4; c++) wmma::fill_fragment(pv[c], 0.0f);
#pragma unroll
            for (int kk = 0; kk < BC; kk += 8) {
                wmma::fragment<wmma::matrix_a, 16, 16, 8, wmma::precision::tf32, wmma::row_major> af;
                wmma::load_matrix_sync(af, &Ss[(wid * 16) * LDF + kk], LDF);
#pragma unroll
                for (int c = 0; c < 4; c++) {
                    wmma::fragment<wmma::matrix_b, 16, 16, 8, wmma::precision::tf32, wmma::row_major> bf;
                    wmma::load_matrix_sync(bf, &Vs[kk * LDF + c * 16], LDF);
                    wmma::mma_sync(pv[c], af, bf, pv[c]);
                }
            }
            __syncwarp();
#pragma unroll
            for (int c = 0; c < 4; c++)
                wmma::store_matrix_sync(&Ss[(wid * 16) * LDF + c * 16], pv[c], LDF,
                                        wmma::mem_row_major);
        }
        __syncwarp();

        // O = O*alpha + PV on owned half-row
#pragma unroll
        for (int c = 0; c < 32; c += 4) {
            float4 o = *(float4*)&Os[rown * LDF + c0 + c];
            float4 t = *(float4*)&Ss[rown * LDF + c0 + c];
            o.x = o.x * alpha + t.x; o.y = o.y * alpha + t.y;
            o.z = o.z * alpha + t.z; o.w = o.w * alpha + t.w;
            *(float4*)&Os[rown * LDF + c0 + c] = o;
        }
    }

    // Epilogue: normalize, write to [B,T,D]
    const int b = bh >> 4, h = bh & (NH - 1);
    const float inv = 1.0f / l_r;
    float* Og = O + ((size_t)(b * T_ + q0 + rown)) * DM + h * HD + c0;
#pragma unroll
    for (int c = 0; c < 32; c += 4) {
        float4 o = *(float4*)&Os[rown * LDF + c0 + c];
        o.x *= inv; o.y *= inv; o.z *= inv; o.w *= inv;
        *(float4*)&Og[c] = o;
    }
}

// ---------------------------------------------------------------------------
extern "C" void kernel_launch(void* const* d_in, const int* in_sizes, int n_in,
                              void* d_out, int out_size)
{
    (void)in_sizes; (void)n_in; (void)out_size;
    const float* x  = (const float*)d_in[0];
    const float* Wq = (const float*)d_in[1];
    const float* Wk = (const float*)d_in[2];
    const float* Wv = (const float*)d_in[3];
    const float* Wo = (const float*)d_in[4];
    const float* qw = (const float*)d_in[5];
    const float* kw = (const float*)d_in[6];
    float* out = (float*)d_out;

    float *qp, *kp, *vp, *ap;
    cudaGetSymbolAddress((void**)&qp, g_q);
    cudaGetSymbolAddress((void**)&kp, g_k);
    cudaGetSymbolAddress((void**)&vp, g_v);
    cudaGetSymbolAddress((void**)&ap, g_attn);

    const int FLASH_SMEM = (3 * BR * LDF + 2 * BC * LDF) * 4;   // 139264 B
    cudaFuncSetAttribute(flash_kernel,
                         cudaFuncAttributeMaxDynamicSharedMemorySize, FLASH_SMEM);

    dim3 gq(DM / 128, ROWS / 128, 3);   // (8, 32, 3)
    qkv_gemm<<<gq, 256>>>(x, Wq, Wk, Wv, qp, kp, vp);

    rmsrope_kernel<<<B_ * NH * T_ / 8, 256>>>(qp, qw);
    rmsrope_kernel<<<B_ * NH * T_ / 8, 256>>>(kp, kw);

    flash_kernel<<<dim3(T_ / BR, B_ * NH), 256, FLASH_SMEM>>>(qp, kp, vp, ap);

    dim3 go(DM / 128, ROWS / 128);      // (8, 32)
    oproj_gemm<<<go, 256>>>(ap, Wo, out);
}